// round 7
// baseline (speedup 1.0000x reference)
#include <cuda_runtime.h>
#include <cuda_fp16.h>
#include <stdint.h>

#define N_NODES 50000
#define N_EDGES 800000
#define C 128
#define BN_EPS 1e-5f

#define NB 148
#define NTH 1024
#define NODES_PER_BLOCK ((N_NODES + NB - 1) / NB)   // 338
#define SCAN_TILES ((N_NODES + NTH - 1) / NTH)      // 49
#define E4 (N_EDGES / 4)                            // 200000
#define TTOT (NB * NTH)                             // 151552

// ---------------- device scratch (static, no allocation) ----------------
__device__ int     d_counts[N_NODES];        // zero-init; reset inside k_edges each run
__device__ int     d_offsets[N_NODES + 1];
__device__ int     d_cursor[N_NODES];
__device__ int     d_csr[N_EDGES];           // src row only (4B/edge)
__device__ float   d_dinv[N_NODES];
__device__ __half2 d_h2[N_NODES * 64];       // fp16 h = x@W (unscaled)
__device__ __half2 d_aggh[N_NODES * 64];     // fp16 pre-BN output
__device__ float   d_bnpart[NB * 256];
__device__ int     d_blocksum[SCAN_TILES];
__device__ int     d_barc;                   // barrier arrive counter (self-resetting)
__device__ int     d_gen;                    // barrier generation (monotone)

// ---------------- helpers ----------------
__device__ __forceinline__ uint32_t f2tf(float f) {
    uint32_t u; asm("cvt.rna.tf32.f32 %0, %1;" : "=r"(u) : "f"(f)); return u;
}
__device__ __forceinline__ void ldsm4(uint32_t& r0, uint32_t& r1, uint32_t& r2, uint32_t& r3, uint32_t addr) {
    asm volatile("ldmatrix.sync.aligned.m8n8.x4.shared.b16 {%0,%1,%2,%3}, [%4];"
                 : "=r"(r0), "=r"(r1), "=r"(r2), "=r"(r3) : "r"(addr));
}
__device__ __forceinline__ void mma_tf32(float* d, const uint32_t* a, const uint32_t* b) {
    asm volatile("mma.sync.aligned.m16n8k8.row.col.f32.tf32.tf32.f32 "
                 "{%0,%1,%2,%3},{%4,%5,%6,%7},{%8,%9},{%0,%1,%2,%3};"
                 : "+f"(d[0]), "+f"(d[1]), "+f"(d[2]), "+f"(d[3])
                 : "r"(a[0]), "r"(a[1]), "r"(a[2]), "r"(a[3]), "r"(b[0]), "r"(b[1]));
}
__device__ __forceinline__ float4 h2f4(uint2 u) {
    __half2 h0 = *(__half2*)&u.x, h1 = *(__half2*)&u.y;
    float2 f0 = __half22float2(h0), f1 = __half22float2(h1);
    return make_float4(f0.x, f0.y, f1.x, f1.y);
}
// grid-wide barrier: requires all gridDim.x blocks resident; gen is monotone (replay-safe)
__device__ __forceinline__ void grid_barrier() {
    __syncthreads();
    if (threadIdx.x == 0) {
        __threadfence();
        int g = atomicAdd(&d_gen, 0);
        if (atomicAdd(&d_barc, 1) == (int)gridDim.x - 1) {
            d_barc = 0;
            __threadfence();
            atomicAdd(&d_gen, 1);
        } else {
            while (atomicAdd(&d_gen, 0) == g) { }
        }
    }
    __syncthreads();
    __threadfence();
}

// ---------------- 1: fused edge pipeline (count + scan + fill), persistent ----------------
__global__ __launch_bounds__(NTH, 1) void k_edges(const int* __restrict__ ei) {
    const int t = threadIdx.x, lane = t & 31, w = t >> 5;
    const int g = blockIdx.x * NTH + t;

    // ---- phase A: load owned edge slots into registers, count targets ----
    const bool v1 = (g + TTOT) < E4;          // slot 0 (g) always valid: TTOT < E4
    int4 c0 = *(const int4*)(ei + N_EDGES + 4 * g);
    int4 r0 = *(const int4*)(ei + 4 * g);
    int4 c1 = make_int4(0, 0, 0, 0), r1 = make_int4(0, 0, 0, 0);
    if (v1) {
        c1 = *(const int4*)(ei + N_EDGES + 4 * (g + TTOT));
        r1 = *(const int4*)(ei + 4 * (g + TTOT));
    }
    atomicAdd(&d_counts[c0.x], 1); atomicAdd(&d_counts[c0.y], 1);
    atomicAdd(&d_counts[c0.z], 1); atomicAdd(&d_counts[c0.w], 1);
    if (v1) {
        atomicAdd(&d_counts[c1.x], 1); atomicAdd(&d_counts[c1.y], 1);
        atomicAdd(&d_counts[c1.z], 1); atomicAdd(&d_counts[c1.w], 1);
    }

    grid_barrier();   // counts complete

    // ---- phase B1: block-local scan over 1024 nodes (blocks 0..48 only) ----
    __shared__ int wsum[32];
    int cnt = 0, incl = 0;
    if (blockIdx.x < SCAN_TILES) {
        const int node = g;
        cnt = (node < N_NODES) ? d_counts[node] : 0;
        int x = cnt;
        #pragma unroll
        for (int o = 1; o < 32; o <<= 1) {
            int y = __shfl_up_sync(0xffffffffu, x, o);
            if (lane >= o) x += y;
        }
        if (lane == 31) wsum[w] = x;
        __syncthreads();
        if (t < 32) {
            int ws = wsum[t];
            #pragma unroll
            for (int o = 1; o < 32; o <<= 1) {
                int y = __shfl_up_sync(0xffffffffu, ws, o);
                if (t >= o) ws += y;
            }
            wsum[t] = ws;
        }
        __syncthreads();
        incl = x + (w > 0 ? wsum[w - 1] : 0);
        if (t == 0) d_blocksum[blockIdx.x] = wsum[31];
    }

    grid_barrier();   // blocksums published

    // ---- phase B2: offsets/cursor/dinv + counts reset ----
    if (blockIdx.x < SCAN_TILES) {
        int off = 0;
        for (int b = 0; b < SCAN_TILES; b++)       // uniform, L1-broadcast
            if (b < blockIdx.x) off += d_blocksum[b];
        const int node = g;
        if (node < N_NODES) {
            int ex = off + incl - cnt;
            d_offsets[node] = ex;
            d_cursor[node]  = ex;
            d_dinv[node]    = rsqrtf((float)(cnt + 1));
            d_counts[node]  = 0;                   // reset for next replay
        }
        if (node == 0) d_offsets[N_NODES] = N_EDGES;
    }

    grid_barrier();   // cursors ready

    // ---- phase C: fill CSR from registered edges (4B stores) ----
    int p;
    p = atomicAdd(&d_cursor[c0.x], 1); d_csr[p] = r0.x;
    p = atomicAdd(&d_cursor[c0.y], 1); d_csr[p] = r0.y;
    p = atomicAdd(&d_cursor[c0.z], 1); d_csr[p] = r0.z;
    p = atomicAdd(&d_cursor[c0.w], 1); d_csr[p] = r0.w;
    if (v1) {
        p = atomicAdd(&d_cursor[c1.x], 1); d_csr[p] = r1.x;
        p = atomicAdd(&d_cursor[c1.y], 1); d_csr[p] = r1.y;
        p = atomicAdd(&d_cursor[c1.z], 1); d_csr[p] = r1.z;
        p = atomicAdd(&d_cursor[c1.w], 1); d_csr[p] = r1.w;
    }
}

// ---------------- 2: tf32 tensor-core GEMM  h2 = fp16(x@W) ----------------
#define PAD_STRIDE 36
__global__ __launch_bounds__(256) void k_gemm(const float* __restrict__ X,
                                              const float* __restrict__ Wm) {
    __shared__ uint32_t As[128 * PAD_STRIDE];
    __shared__ uint32_t BTs[128 * PAD_STRIDE];

    const int tid = threadIdx.x;
    const int lane = tid & 31, wid = tid >> 5;
    const int block_row = blockIdx.x * 128;

    float acc[2][8][4];
    #pragma unroll
    for (int am = 0; am < 2; am++)
        #pragma unroll
        for (int an = 0; an < 8; an++)
            #pragma unroll
            for (int j = 0; j < 4; j++) acc[am][an][j] = 0.f;

    const int wm = wid & 3, wn = wid >> 2;
    const int m0 = wm * 32, n0 = wn * 64;
    const int r8 = lane & 7, sel = lane >> 3;

    for (int kc = 0; kc < 128; kc += 32) {
        #pragma unroll
        for (int p = 0; p < 16; p++) {
            int idx = p * 256 + tid;
            int kk = idx >> 7, n = idx & 127;
            BTs[n * PAD_STRIDE + kk] = f2tf(Wm[(kc + kk) * 128 + n]);
        }
        #pragma unroll
        for (int p = 0; p < 4; p++) {
            int idx = p * 256 + tid;
            int row = idx >> 3, c4 = idx & 7;
            int gr = block_row + row;
            float4 v = make_float4(0.f, 0.f, 0.f, 0.f);
            if (gr < N_NODES) v = *(const float4*)(X + gr * 128 + kc + c4 * 4);
            uint32_t* dst = &As[row * PAD_STRIDE + c4 * 4];
            dst[0] = f2tf(v.x); dst[1] = f2tf(v.y); dst[2] = f2tf(v.z); dst[3] = f2tf(v.w);
        }
        __syncthreads();

        #pragma unroll
        for (int ks = 0; ks < 4; ks++) {
            const int k0 = ks * 8;
            uint32_t a[2][4];
            #pragma unroll
            for (int am = 0; am < 2; am++) {
                int arow = m0 + am * 16 + (sel & 1) * 8 + r8;
                int akk  = k0 + (sel >> 1) * 4;
                uint32_t addr = (uint32_t)__cvta_generic_to_shared(&As[arow * PAD_STRIDE + akk]);
                ldsm4(a[am][0], a[am][1], a[am][2], a[am][3], addr);
            }
            uint32_t b[4][4];
            #pragma unroll
            for (int g = 0; g < 4; g++) {
                int brow = g * 16 + (sel >> 1) * 8 + r8;
                int bkk  = k0 + (sel & 1) * 4;
                uint32_t addr = (uint32_t)__cvta_generic_to_shared(&BTs[(n0 + brow) * PAD_STRIDE + bkk]);
                ldsm4(b[g][0], b[g][1], b[g][2], b[g][3], addr);
            }
            #pragma unroll
            for (int am = 0; am < 2; am++)
                #pragma unroll
                for (int an = 0; an < 8; an++)
                    mma_tf32(acc[am][an], a[am], &b[an >> 1][(an & 1) * 2]);
        }
        __syncthreads();
    }

    const int t4 = lane >> 2, tk = lane & 3;
    #pragma unroll
    for (int am = 0; am < 2; am++) {
        int gr0 = block_row + m0 + am * 16 + t4;
        int gr1 = gr0 + 8;
        #pragma unroll
        for (int an = 0; an < 8; an++) {
            int c2 = (n0 + an * 8) / 2 + tk;
            if (gr0 < N_NODES)
                d_h2[gr0 * 64 + c2] = __floats2half2_rn(acc[am][an][0], acc[am][an][1]);
            if (gr1 < N_NODES)
                d_h2[gr1 * 64 + c2] = __floats2half2_rn(acc[am][an][2], acc[am][an][3]);
        }
    }
}

// ---------------- 3: persistent gather + BN + normalize + ReLU + out ----------------
__global__ __launch_bounds__(NTH, 1) void k_aggout(const float* __restrict__ gamma,
                                                   const float* __restrict__ beta,
                                                   float* __restrict__ out) {
    const int lane = threadIdx.x & 31;
    const int w = threadIdx.x >> 5;
    const int base  = blockIdx.x * NODES_PER_BLOCK;
    const int limit = min(base + NODES_PER_BLOCK, N_NODES);
    const uint2* __restrict__ gv = (const uint2*)d_h2;
    const int* __restrict__ csr = d_csr;

    float4 bnS = make_float4(0.f, 0.f, 0.f, 0.f);
    float4 bnQ = make_float4(0.f, 0.f, 0.f, 0.f);

    // ----- phase 1: aggregate owned nodes -----
    for (int i = base + w; i < limit; i += 32) {
        const int start = d_offsets[i];
        const int end   = d_offsets[i + 1];
        const float di = d_dinv[i];
        float4 hv = h2f4(gv[i * 32 + lane]);
        float4 acc;
        acc.x = di * hv.x; acc.y = di * hv.y; acc.z = di * hv.z; acc.w = di * hv.w;
        for (int p0 = start; p0 < end; p0 += 32) {
            int idx = p0 + lane;
            int r_l = 0; float dr_l = 0.f;
            if (idx < end) { r_l = csr[idx]; dr_l = d_dinv[r_l]; }
            int cnt = min(32, end - p0);
            for (int j = 0; j < cnt; j++) {
                int r   = __shfl_sync(0xffffffffu, r_l, j);
                float dr = __shfl_sync(0xffffffffu, dr_l, j);
                float4 v = h2f4(gv[r * 32 + lane]);
                acc.x += dr * v.x; acc.y += dr * v.y;
                acc.z += dr * v.z; acc.w += dr * v.w;
            }
        }
        acc.x *= di; acc.y *= di; acc.z *= di; acc.w *= di;
        uint2 packed;
        *(__half2*)&packed.x = __floats2half2_rn(acc.x, acc.y);
        *(__half2*)&packed.y = __floats2half2_rn(acc.z, acc.w);
        ((uint2*)d_aggh)[i * 32 + lane] = packed;
        bnS.x += acc.x; bnS.y += acc.y; bnS.z += acc.z; bnS.w += acc.w;
        bnQ.x += acc.x * acc.x; bnQ.y += acc.y * acc.y;
        bnQ.z += acc.z * acc.z; bnQ.w += acc.w * acc.w;
    }

    // ----- block-level BN partial reduce -----
    __shared__ float4 sS[32][32], sQ[32][32];
    sS[w][lane] = bnS; sQ[w][lane] = bnQ;
    __syncthreads();
    if (w == 0) {
        float4 S = sS[0][lane], Q = sQ[0][lane];
        #pragma unroll
        for (int ww = 1; ww < 32; ww++) {
            S.x += sS[ww][lane].x; S.y += sS[ww][lane].y; S.z += sS[ww][lane].z; S.w += sS[ww][lane].w;
            Q.x += sQ[ww][lane].x; Q.y += sQ[ww][lane].y; Q.z += sQ[ww][lane].z; Q.w += sQ[ww][lane].w;
        }
        ((float4*)d_bnpart)[blockIdx.x * 64 + lane]      = S;
        ((float4*)d_bnpart)[blockIdx.x * 64 + 32 + lane] = Q;
    }

    grid_barrier();

    // ----- BN finalize (redundant per block; L2-hot) -----
    __shared__ float s_scale[C], s_shift[C];
    {
        const int c = threadIdx.x & 127;
        const int slice = threadIdx.x >> 7;
        float s = 0.f, q = 0.f;
        for (int b = slice; b < NB; b += 8) {
            s += d_bnpart[b * 256 + c];
            q += d_bnpart[b * 256 + 128 + c];
        }
        __shared__ float ss[8][128], sq[8][128];
        ss[slice][c] = s; sq[slice][c] = q;
        __syncthreads();
        if (slice == 0) {
            #pragma unroll
            for (int k = 1; k < 8; k++) { s += ss[k][c]; q += sq[k][c]; }
            float inv_n = 1.f / (float)N_NODES;
            float m = s * inv_n;
            float var = q * inv_n - m * m;
            float istd = rsqrtf(var + BN_EPS);
            float sc = gamma[c] * istd;
            s_scale[c] = sc;
            s_shift[c] = beta[c] - m * sc;
        }
        __syncthreads();
    }

    // ----- phase 2: normalize + ReLU + write own slice -----
    const int f0 = base * 32, f1 = limit * 32;
    for (int f = f0 + threadIdx.x; f < f1; f += NTH) {
        int c4 = f & 31;
        float4 v = h2f4(((const uint2*)d_aggh)[f]);
        float4 sc = ((const float4*)s_scale)[c4];
        float4 sh = ((const float4*)s_shift)[c4];
        float4 y;
        y.x = fmaxf(v.x * sc.x + sh.x, 0.f);
        y.y = fmaxf(v.y * sc.y + sh.y, 0.f);
        y.z = fmaxf(v.z * sc.z + sh.z, 0.f);
        y.w = fmaxf(v.w * sc.w + sh.w, 0.f);
        ((float4*)out)[f] = y;
    }
}

// ---------------- launch ----------------
extern "C" void kernel_launch(void* const* d_in, const int* in_sizes, int n_in,
                              void* d_out, int out_size) {
    const float* x     = (const float*)d_in[0];
    const float* W     = (const float*)d_in[1];
    // d_in[2] = bias : cancels exactly through training-mode BatchNorm
    const float* gamma = (const float*)d_in[3];
    const float* beta  = (const float*)d_in[4];
    const int*   ei    = (const int*)d_in[5];
    float* out = (float*)d_out;

    cudaStream_t s1;
    cudaStreamCreateWithFlags(&s1, cudaStreamNonBlocking);
    cudaEvent_t e0, e1;
    cudaEventCreateWithFlags(&e0, cudaEventDisableTiming);
    cudaEventCreateWithFlags(&e1, cudaEventDisableTiming);

    // fork: GEMM depends only on x, W
    cudaEventRecord(e0, 0);
    cudaStreamWaitEvent(s1, e0, 0);
    k_gemm<<<(N_NODES + 127) / 128, 256, 0, s1>>>(x, W);
    cudaEventRecord(e1, s1);

    // legacy stream: fused edge pipeline (persistent, grid barriers)
    k_edges<<<NB, NTH>>>(ei);

    // join: fused aggregate + BN + output
    cudaStreamWaitEvent(0, e1, 0);
    k_aggout<<<NB, NTH>>>(gamma, beta, out);
}

// round 8
// speedup vs baseline: 1.0573x; 1.0573x over previous
#include <cuda_runtime.h>
#include <cuda_fp16.h>
#include <stdint.h>

#define N_NODES 50000
#define N_EDGES 800000
#define C 128
#define BN_EPS 1e-5f

#define SCAN_B 1024
#define NTILES ((N_NODES + SCAN_B - 1) / SCAN_B)   // 49
#define NB 148
#define NTH 1024
#define NODES_PER_BLOCK ((N_NODES + NB - 1) / NB)  // 338
#define E8 (N_EDGES / 8)                           // 100000

// ---------------- device scratch (static, no allocation) ----------------
__device__ int     d_counts[N_NODES];        // zero-init; reset by k_scan each run
__device__ int     d_offsets[N_NODES + 1];
__device__ int     d_cursor[N_NODES];
__device__ int     d_csr[N_EDGES];           // src row only (4B/edge)
__device__ float   d_dinv[N_NODES];
__device__ __half2 d_h2[N_NODES * 64];       // fp16 h = x@W (unscaled)
__device__ __half2 d_aggh[N_NODES * 64];     // fp16 pre-BN output
__device__ float   d_bnpart[NB * 256];
__device__ int     d_tile_pack[NTILES];      // (1<<30)|aggregate ; reset by aggout blk0
__device__ int     d_barc;                   // barrier arrive counter (self-resetting)
__device__ int     d_gen;                    // barrier generation (monotone)

// ---------------- helpers ----------------
__device__ __forceinline__ uint32_t f2tf(float f) {
    uint32_t u; asm("cvt.rna.tf32.f32 %0, %1;" : "=r"(u) : "f"(f)); return u;
}
__device__ __forceinline__ void ldsm4(uint32_t& r0, uint32_t& r1, uint32_t& r2, uint32_t& r3, uint32_t addr) {
    asm volatile("ldmatrix.sync.aligned.m8n8.x4.shared.b16 {%0,%1,%2,%3}, [%4];"
                 : "=r"(r0), "=r"(r1), "=r"(r2), "=r"(r3) : "r"(addr));
}
__device__ __forceinline__ void mma_tf32(float* d, const uint32_t* a, const uint32_t* b) {
    asm volatile("mma.sync.aligned.m16n8k8.row.col.f32.tf32.tf32.f32 "
                 "{%0,%1,%2,%3},{%4,%5,%6,%7},{%8,%9},{%0,%1,%2,%3};"
                 : "+f"(d[0]), "+f"(d[1]), "+f"(d[2]), "+f"(d[3])
                 : "r"(a[0]), "r"(a[1]), "r"(a[2]), "r"(a[3]), "r"(b[0]), "r"(b[1]));
}
__device__ __forceinline__ float4 h2f4(uint2 u) {
    __half2 h0 = *(__half2*)&u.x, h1 = *(__half2*)&u.y;
    float2 f0 = __half22float2(h0), f1 = __half22float2(h1);
    return make_float4(f0.x, f0.y, f1.x, f1.y);
}
__device__ __forceinline__ void grid_barrier() {
    __syncthreads();
    if (threadIdx.x == 0) {
        __threadfence();
        int g = atomicAdd(&d_gen, 0);
        if (atomicAdd(&d_barc, 1) == (int)gridDim.x - 1) {
            d_barc = 0;
            __threadfence();
            atomicAdd(&d_gen, 1);
        } else {
            while (atomicAdd(&d_gen, 0) == g) { }
        }
    }
    __syncthreads();
    __threadfence();
}

// ---------------- 1: per-target edge counts (8 edges/thread for MLP) ----------------
__global__ void k_count(const int* __restrict__ ei) {
    int t = blockIdx.x * blockDim.x + threadIdx.x;
    if (t >= E8) return;
    int4 c0 = *(const int4*)(ei + N_EDGES + 8 * t);
    int4 c1 = *(const int4*)(ei + N_EDGES + 8 * t + 4);
    atomicAdd(&d_counts[c0.x], 1); atomicAdd(&d_counts[c0.y], 1);
    atomicAdd(&d_counts[c0.z], 1); atomicAdd(&d_counts[c0.w], 1);
    atomicAdd(&d_counts[c1.x], 1); atomicAdd(&d_counts[c1.y], 1);
    atomicAdd(&d_counts[c1.z], 1); atomicAdd(&d_counts[c1.w], 1);
}

// ---------------- 2: single-pass scan (decoupled lookback) + dinv + cursor ----------------
__global__ __launch_bounds__(SCAN_B) void k_scan() {
    const int b = blockIdx.x, t = threadIdx.x, lane = t & 31, w = t >> 5;
    const int i = b * SCAN_B + t;
    const int cnt = (i < N_NODES) ? d_counts[i] : 0;

    int x = cnt;
    #pragma unroll
    for (int o = 1; o < 32; o <<= 1) {
        int y = __shfl_up_sync(0xffffffffu, x, o);
        if (lane >= o) x += y;
    }
    __shared__ int wsum[32];
    if (lane == 31) wsum[w] = x;
    __syncthreads();
    if (t < 32) {
        int ws = wsum[t];
        #pragma unroll
        for (int o = 1; o < 32; o <<= 1) {
            int y = __shfl_up_sync(0xffffffffu, ws, o);
            if (t >= o) ws += y;
        }
        wsum[t] = ws;
        if (t == 31) atomicExch(&d_tile_pack[b], (1 << 30) | ws);
    }
    __syncthreads();
    const int incl = x + (w > 0 ? wsum[w - 1] : 0);

    __shared__ int s_excl;
    if (t == 0) s_excl = 0;
    __syncthreads();
    if (t < b) {
        int v;
        do { v = atomicAdd(&d_tile_pack[t], 0); } while (!(v & (1 << 30)));
        atomicAdd(&s_excl, v & 0x3FFFFFFF);
    }
    __syncthreads();

    if (i < N_NODES) {
        int ex = s_excl + incl - cnt;
        d_offsets[i] = ex;
        d_cursor[i]  = ex;
        d_dinv[i]    = rsqrtf((float)(cnt + 1));
        d_counts[i]  = 0;                 // reset for next replay
    }
    if (i == 0) d_offsets[N_NODES] = N_EDGES;
}

// ---------------- 3: fill CSR (row only, 8 edges/thread) ----------------
__global__ void k_fill(const int* __restrict__ ei) {
    int t = blockIdx.x * blockDim.x + threadIdx.x;
    if (t >= E8) return;
    int4 r0 = *(const int4*)(ei + 8 * t);
    int4 r1 = *(const int4*)(ei + 8 * t + 4);
    int4 c0 = *(const int4*)(ei + N_EDGES + 8 * t);
    int4 c1 = *(const int4*)(ei + N_EDGES + 8 * t + 4);
    int p;
    p = atomicAdd(&d_cursor[c0.x], 1); d_csr[p] = r0.x;
    p = atomicAdd(&d_cursor[c0.y], 1); d_csr[p] = r0.y;
    p = atomicAdd(&d_cursor[c0.z], 1); d_csr[p] = r0.z;
    p = atomicAdd(&d_cursor[c0.w], 1); d_csr[p] = r0.w;
    p = atomicAdd(&d_cursor[c1.x], 1); d_csr[p] = r1.x;
    p = atomicAdd(&d_cursor[c1.y], 1); d_csr[p] = r1.y;
    p = atomicAdd(&d_cursor[c1.z], 1); d_csr[p] = r1.z;
    p = atomicAdd(&d_cursor[c1.w], 1); d_csr[p] = r1.w;
}

// ---------------- 4: tf32 GEMM v2 (BM=64, register-prefetch pipeline) ----------------
#define PAD_STRIDE 36
__global__ __launch_bounds__(256) void k_gemm(const float* __restrict__ X,
                                              const float* __restrict__ Wm) {
    __shared__ uint32_t As[64 * PAD_STRIDE];    // A chunk: 64 rows x 32 k (tf32)
    __shared__ uint32_t BTs[128 * PAD_STRIDE];  // W^T chunk: 128 n x 32 k (tf32)

    const int tid = threadIdx.x;
    const int lane = tid & 31, wid = tid >> 5;
    const int block_row = blockIdx.x * 64;

    float acc[2][4][4];
    #pragma unroll
    for (int am = 0; am < 2; am++)
        #pragma unroll
        for (int an = 0; an < 4; an++)
            #pragma unroll
            for (int j = 0; j < 4; j++) acc[am][an][j] = 0.f;

    const int wm = wid & 1, wn = wid >> 1;     // 2 x 4 warp grid
    const int m0 = wm * 32, n0 = wn * 32;
    const int r8 = lane & 7, sel = lane >> 3;

    // A staging slots: 2 float4/thread per chunk
    const int aRow0 = tid >> 3, aRow1 = (256 + tid) >> 3;   // 0..31, 32..63
    const int aC4   = (tid & 7) * 4;
    // W staging: 16 floats/thread per chunk (idx = p*256+tid -> kk=idx>>7, n=idx&127)

    float4 aP[2];
    float  wP[16];
    // ---- prologue: load chunk 0 into regs ----
    {
        int gr0 = block_row + aRow0, gr1 = block_row + aRow1;
        aP[0] = (gr0 < N_NODES) ? *(const float4*)(X + gr0 * 128 + aC4)
                                : make_float4(0.f, 0.f, 0.f, 0.f);
        aP[1] = (gr1 < N_NODES) ? *(const float4*)(X + gr1 * 128 + aC4)
                                : make_float4(0.f, 0.f, 0.f, 0.f);
        #pragma unroll
        for (int p = 0; p < 16; p++) {
            int idx = p * 256 + tid;
            wP[p] = Wm[((idx >> 7)) * 128 + (idx & 127)];
        }
    }

    for (int kci = 0; kci < 4; kci++) {
        // ---- store staged regs to smem (tf32) ----
        {
            uint32_t* d0 = &As[aRow0 * PAD_STRIDE + aC4];
            d0[0] = f2tf(aP[0].x); d0[1] = f2tf(aP[0].y); d0[2] = f2tf(aP[0].z); d0[3] = f2tf(aP[0].w);
            uint32_t* d1 = &As[aRow1 * PAD_STRIDE + aC4];
            d1[0] = f2tf(aP[1].x); d1[1] = f2tf(aP[1].y); d1[2] = f2tf(aP[1].z); d1[3] = f2tf(aP[1].w);
            #pragma unroll
            for (int p = 0; p < 16; p++) {
                int idx = p * 256 + tid;
                BTs[(idx & 127) * PAD_STRIDE + (idx >> 7)] = f2tf(wP[p]);
            }
        }
        __syncthreads();

        // ---- prefetch next chunk into regs (overlaps compute below) ----
        if (kci < 3) {
            const int kc = (kci + 1) * 32;
            int gr0 = block_row + aRow0, gr1 = block_row + aRow1;
            aP[0] = (gr0 < N_NODES) ? *(const float4*)(X + gr0 * 128 + kc + aC4)
                                    : make_float4(0.f, 0.f, 0.f, 0.f);
            aP[1] = (gr1 < N_NODES) ? *(const float4*)(X + gr1 * 128 + kc + aC4)
                                    : make_float4(0.f, 0.f, 0.f, 0.f);
            #pragma unroll
            for (int p = 0; p < 16; p++) {
                int idx = p * 256 + tid;
                wP[p] = Wm[(kc + (idx >> 7)) * 128 + (idx & 127)];
            }
        }

        // ---- compute on staged chunk ----
        #pragma unroll
        for (int ks = 0; ks < 4; ks++) {
            const int k0 = ks * 8;
            uint32_t a[2][4];
            #pragma unroll
            for (int am = 0; am < 2; am++) {
                int arow = m0 + am * 16 + (sel & 1) * 8 + r8;
                int akk  = k0 + (sel >> 1) * 4;
                uint32_t addr = (uint32_t)__cvta_generic_to_shared(&As[arow * PAD_STRIDE + akk]);
                ldsm4(a[am][0], a[am][1], a[am][2], a[am][3], addr);
            }
            uint32_t b[2][4];
            #pragma unroll
            for (int g = 0; g < 2; g++) {
                int brow = n0 + g * 16 + (sel >> 1) * 8 + r8;
                int bkk  = k0 + (sel & 1) * 4;
                uint32_t addr = (uint32_t)__cvta_generic_to_shared(&BTs[brow * PAD_STRIDE + bkk]);
                ldsm4(b[g][0], b[g][1], b[g][2], b[g][3], addr);
            }
            #pragma unroll
            for (int am = 0; am < 2; am++)
                #pragma unroll
                for (int an = 0; an < 4; an++)
                    mma_tf32(acc[am][an], a[am], &b[an >> 1][(an & 1) * 2]);
        }
        __syncthreads();
    }

    // ---- epilogue: fp16 store ----
    const int t4 = lane >> 2, tk = lane & 3;
    #pragma unroll
    for (int am = 0; am < 2; am++) {
        int gr0 = block_row + m0 + am * 16 + t4;
        int gr1 = gr0 + 8;
        #pragma unroll
        for (int an = 0; an < 4; an++) {
            int c2 = (n0 + an * 8) / 2 + tk;
            if (gr0 < N_NODES)
                d_h2[gr0 * 64 + c2] = __floats2half2_rn(acc[am][an][0], acc[am][an][1]);
            if (gr1 < N_NODES)
                d_h2[gr1 * 64 + c2] = __floats2half2_rn(acc[am][an][2], acc[am][an][3]);
        }
    }
}

// ---------------- 5: persistent gather + BN + normalize + ReLU + out ----------------
__global__ __launch_bounds__(NTH, 1) void k_aggout(const float* __restrict__ gamma,
                                                   const float* __restrict__ beta,
                                                   float* __restrict__ out) {
    const int lane = threadIdx.x & 31;
    const int w = threadIdx.x >> 5;
    const int base  = blockIdx.x * NODES_PER_BLOCK;
    const int limit = min(base + NODES_PER_BLOCK, N_NODES);
    const uint2* __restrict__ gv = (const uint2*)d_h2;
    const int* __restrict__ csr = d_csr;

    float4 bnS = make_float4(0.f, 0.f, 0.f, 0.f);
    float4 bnQ = make_float4(0.f, 0.f, 0.f, 0.f);

    for (int i = base + w; i < limit; i += 32) {
        const int start = d_offsets[i];
        const int end   = d_offsets[i + 1];
        const float di = d_dinv[i];
        float4 hv = h2f4(gv[i * 32 + lane]);
        float4 acc;
        acc.x = di * hv.x; acc.y = di * hv.y; acc.z = di * hv.z; acc.w = di * hv.w;
        for (int p0 = start; p0 < end; p0 += 32) {
            int idx = p0 + lane;
            int r_l = 0; float dr_l = 0.f;
            if (idx < end) { r_l = csr[idx]; dr_l = d_dinv[r_l]; }
            int cnt = min(32, end - p0);
            for (int j = 0; j < cnt; j++) {
                int r    = __shfl_sync(0xffffffffu, r_l, j);
                float dr = __shfl_sync(0xffffffffu, dr_l, j);
                float4 v = h2f4(gv[r * 32 + lane]);
                acc.x += dr * v.x; acc.y += dr * v.y;
                acc.z += dr * v.z; acc.w += dr * v.w;
            }
        }
        acc.x *= di; acc.y *= di; acc.z *= di; acc.w *= di;
        uint2 packed;
        *(__half2*)&packed.x = __floats2half2_rn(acc.x, acc.y);
        *(__half2*)&packed.y = __floats2half2_rn(acc.z, acc.w);
        ((uint2*)d_aggh)[i * 32 + lane] = packed;
        bnS.x += acc.x; bnS.y += acc.y; bnS.z += acc.z; bnS.w += acc.w;
        bnQ.x += acc.x * acc.x; bnQ.y += acc.y * acc.y;
        bnQ.z += acc.z * acc.z; bnQ.w += acc.w * acc.w;
    }

    __shared__ float4 sS[32][32], sQ[32][32];
    sS[w][lane] = bnS; sQ[w][lane] = bnQ;
    if (blockIdx.x == 0 && threadIdx.x < NTILES) d_tile_pack[threadIdx.x] = 0;  // scan reset
    __syncthreads();
    if (w == 0) {
        float4 S = sS[0][lane], Q = sQ[0][lane];
        #pragma unroll
        for (int ww = 1; ww < 32; ww++) {
            S.x += sS[ww][lane].x; S.y += sS[ww][lane].y; S.z += sS[ww][lane].z; S.w += sS[ww][lane].w;
            Q.x += sQ[ww][lane].x; Q.y += sQ[ww][lane].y; Q.z += sQ[ww][lane].z; Q.w += sQ[ww][lane].w;
        }
        ((float4*)d_bnpart)[blockIdx.x * 64 + lane]      = S;
        ((float4*)d_bnpart)[blockIdx.x * 64 + 32 + lane] = Q;
    }

    grid_barrier();

    __shared__ float s_scale[C], s_shift[C];
    {
        const int c = threadIdx.x & 127;
        const int slice = threadIdx.x >> 7;
        float s = 0.f, q = 0.f;
        for (int b = slice; b < NB; b += 8) {
            s += d_bnpart[b * 256 + c];
            q += d_bnpart[b * 256 + 128 + c];
        }
        __shared__ float ss[8][128], sq[8][128];
        ss[slice][c] = s; sq[slice][c] = q;
        __syncthreads();
        if (slice == 0) {
            #pragma unroll
            for (int k = 1; k < 8; k++) { s += ss[k][c]; q += sq[k][c]; }
            float inv_n = 1.f / (float)N_NODES;
            float m = s * inv_n;
            float var = q * inv_n - m * m;
            float istd = rsqrtf(var + BN_EPS);
            float sc = gamma[c] * istd;
            s_scale[c] = sc;
            s_shift[c] = beta[c] - m * sc;
        }
        __syncthreads();
    }

    const int f0 = base * 32, f1 = limit * 32;
    for (int f = f0 + threadIdx.x; f < f1; f += NTH) {
        int c4 = f & 31;
        float4 v = h2f4(((const uint2*)d_aggh)[f]);
        float4 sc = ((const float4*)s_scale)[c4];
        float4 sh = ((const float4*)s_shift)[c4];
        float4 y;
        y.x = fmaxf(v.x * sc.x + sh.x, 0.f);
        y.y = fmaxf(v.y * sc.y + sh.y, 0.f);
        y.z = fmaxf(v.z * sc.z + sh.z, 0.f);
        y.w = fmaxf(v.w * sc.w + sh.w, 0.f);
        ((float4*)out)[f] = y;
    }
}

// ---------------- launch ----------------
extern "C" void kernel_launch(void* const* d_in, const int* in_sizes, int n_in,
                              void* d_out, int out_size) {
    const float* x     = (const float*)d_in[0];
    const float* W     = (const float*)d_in[1];
    // d_in[2] = bias : cancels exactly through training-mode BatchNorm
    const float* gamma = (const float*)d_in[3];
    const float* beta  = (const float*)d_in[4];
    const int*   ei    = (const int*)d_in[5];
    float* out = (float*)d_out;

    cudaStream_t s1;
    cudaStreamCreateWithFlags(&s1, cudaStreamNonBlocking);
    cudaEvent_t e0, e1;
    cudaEventCreateWithFlags(&e0, cudaEventDisableTiming);
    cudaEventCreateWithFlags(&e1, cudaEventDisableTiming);

    // fork: GEMM depends only on x, W
    cudaEventRecord(e0, 0);
    cudaStreamWaitEvent(s1, e0, 0);
    k_gemm<<<(N_NODES + 63) / 64, 256, 0, s1>>>(x, W);
    cudaEventRecord(e1, s1);

    // legacy stream: edge pipeline
    k_count<<<(E8 + 255) / 256, 256>>>(ei);
    k_scan<<<NTILES, SCAN_B>>>();
    k_fill<<<(E8 + 255) / 256, 256>>>(ei);

    // join: fused aggregate + BN + output
    cudaStreamWaitEvent(0, e1, 0);
    k_aggout<<<NB, NTH>>>(gamma, beta, out);
}